// round 2
// baseline (speedup 1.0000x reference)
#include <cuda_runtime.h>
#include <cuda_bf16.h>
#include <math.h>

// Problem constants
#define BATCH 2
#define SEQ   4096
#define DIM   512
#define ROWS  (BATCH * SEQ)          // 8192

// Scratch (static device globals — no allocations)
__device__ float g_Q[ROWS * DIM];
__device__ float g_K[ROWS * DIM];
__device__ float g_V[ROWS * DIM];
__device__ float g_P[(size_t)BATCH * SEQ * SEQ];   // scores / exp-weights (134 MB)
__device__ float g_inv[ROWS];                      // 1/rowsum

// ---------------------------------------------------------------------------
// Tiled SGEMM: C = alpha * A @ B(T)  [+ per-row scale]
// BM=BN=128, BK=8, 256 threads, 8x8 microtile per thread.
// A: [M,K] row-major. NN: B [K,N] row-major. NT: B [N,K] row-major (C=A@B^T).
// Batch via blockIdx.z with element strides.
// ---------------------------------------------------------------------------
#define BM 128
#define BN 128
#define BKK 8
#define TM 8
#define TN 8

template <bool TRANS_B, bool ROW_SCALE>
__global__ __launch_bounds__(256, 2)
void sgemm_kernel(const float* __restrict__ A,
                  const float* __restrict__ B,
                  float* __restrict__ C,
                  int M, int N, int K, float alpha,
                  size_t strideA, size_t strideB, size_t strideC,
                  const float* __restrict__ row_scale, int strideScale)
{
    __shared__ __align__(16) float As[BKK][BM];
    __shared__ __align__(16) float Bs[BKK][BN];

    A += (size_t)blockIdx.z * strideA;
    B += (size_t)blockIdx.z * strideB;
    C += (size_t)blockIdx.z * strideC;

    const int bm = blockIdx.y * BM;
    const int bn = blockIdx.x * BN;
    const int tid = threadIdx.x;

    // A tile load: 128 rows x 8 k-cols -> 256 float4 (one per thread)
    const int a_row = tid >> 1;
    const int a_col = (tid & 1) * 4;
    // B tile load (NN): 8 k-rows x 128 cols
    const int bn_row = tid >> 5;
    const int bn_col = (tid & 31) * 4;

    const int tr = tid >> 4;   // 0..15
    const int tc = tid & 15;   // 0..15

    float acc[TM][TN];
#pragma unroll
    for (int i = 0; i < TM; i++)
#pragma unroll
        for (int j = 0; j < TN; j++) acc[i][j] = 0.f;

    for (int k0 = 0; k0 < K; k0 += BKK) {
        // load A tile (transposed into smem: As[k][m])
        {
            float4 av = *(const float4*)&A[(size_t)(bm + a_row) * K + k0 + a_col];
            As[a_col + 0][a_row] = av.x;
            As[a_col + 1][a_row] = av.y;
            As[a_col + 2][a_row] = av.z;
            As[a_col + 3][a_row] = av.w;
        }
        // load B tile
        if (TRANS_B) {
            // B is [N,K]: rows bn..bn+127, cols k0..k0+7  (same shape as A load)
            float4 bv = *(const float4*)&B[(size_t)(bn + a_row) * K + k0 + a_col];
            Bs[a_col + 0][a_row] = bv.x;
            Bs[a_col + 1][a_row] = bv.y;
            Bs[a_col + 2][a_row] = bv.z;
            Bs[a_col + 3][a_row] = bv.w;
        } else {
            float4 bv = *(const float4*)&B[(size_t)(k0 + bn_row) * N + bn + bn_col];
            *(float4*)&Bs[bn_row][bn_col] = bv;
        }
        __syncthreads();

#pragma unroll
        for (int kk = 0; kk < BKK; kk++) {
            float4 a0 = *(const float4*)&As[kk][tr * TM];
            float4 a1 = *(const float4*)&As[kk][tr * TM + 4];
            float4 b0 = *(const float4*)&Bs[kk][tc * TN];
            float4 b1 = *(const float4*)&Bs[kk][tc * TN + 4];
            float ar[TM] = {a0.x, a0.y, a0.z, a0.w, a1.x, a1.y, a1.z, a1.w};
            float br[TN] = {b0.x, b0.y, b0.z, b0.w, b1.x, b1.y, b1.z, b1.w};
#pragma unroll
            for (int i = 0; i < TM; i++)
#pragma unroll
                for (int j = 0; j < TN; j++)
                    acc[i][j] = fmaf(ar[i], br[j], acc[i][j]);
        }
        __syncthreads();
    }

    // epilogue
#pragma unroll
    for (int i = 0; i < TM; i++) {
        const int row = bm + tr * TM + i;
        float s = alpha;
        if (ROW_SCALE) s *= row_scale[(size_t)blockIdx.z * strideScale + row];
        float4 o0, o1;
        o0.x = acc[i][0] * s; o0.y = acc[i][1] * s;
        o0.z = acc[i][2] * s; o0.w = acc[i][3] * s;
        o1.x = acc[i][4] * s; o1.y = acc[i][5] * s;
        o1.z = acc[i][6] * s; o1.w = acc[i][7] * s;
        *(float4*)&C[(size_t)row * N + bn + tc * TN + 0] = o0;
        *(float4*)&C[(size_t)row * N + bn + tc * TN + 4] = o1;
    }
}

// ---------------------------------------------------------------------------
// Row softmax (in place): p[c] = exp(p[c]-max); store 1/sum per row.
// Normalization is folded into the context GEMM epilogue.
// ---------------------------------------------------------------------------
__global__ void softmax_exp_kernel(float* __restrict__ P,
                                   float* __restrict__ inv_sum,
                                   int ncols)
{
    __shared__ float red[256];
    const size_t row = blockIdx.x;
    float* p = P + row * (size_t)ncols;
    const int tid = threadIdx.x;

    float m = -3.0e38f;
    for (int c = tid * 4; c < ncols; c += 256 * 4) {
        float4 v = *(const float4*)&p[c];
        m = fmaxf(m, fmaxf(fmaxf(v.x, v.y), fmaxf(v.z, v.w)));
    }
    red[tid] = m;
    __syncthreads();
    for (int s = 128; s > 0; s >>= 1) {
        if (tid < s) red[tid] = fmaxf(red[tid], red[tid + s]);
        __syncthreads();
    }
    m = red[0];
    __syncthreads();

    float sum = 0.f;
    for (int c = tid * 4; c < ncols; c += 256 * 4) {
        float4 v = *(const float4*)&p[c];
        v.x = __expf(v.x - m);
        v.y = __expf(v.y - m);
        v.z = __expf(v.z - m);
        v.w = __expf(v.w - m);
        sum += v.x + v.y + v.z + v.w;
        *(float4*)&p[c] = v;
    }
    red[tid] = sum;
    __syncthreads();
    for (int s = 128; s > 0; s >>= 1) {
        if (tid < s) red[tid] += red[tid + s];
        __syncthreads();
    }
    if (tid == 0) inv_sum[row] = 1.0f / red[0];
}

// ---------------------------------------------------------------------------
extern "C" void kernel_launch(void* const* d_in, const int* in_sizes, int n_in,
                              void* d_out, int out_size)
{
    const float* x  = (const float*)d_in[0];  // [2,4096,512]
    const float* Wq = (const float*)d_in[1];  // [512,512]
    const float* Wk = (const float*)d_in[2];
    const float* Wv = (const float*)d_in[3];
    float* out = (float*)d_out;               // [2,4096,512]

    float *Q, *K, *V, *P, *inv;
    cudaGetSymbolAddress((void**)&Q,   g_Q);
    cudaGetSymbolAddress((void**)&K,   g_K);
    cudaGetSymbolAddress((void**)&V,   g_V);
    cudaGetSymbolAddress((void**)&P,   g_P);
    cudaGetSymbolAddress((void**)&inv, g_inv);

    const float inv_sqrt_d = 0.04419417382415922f;  // 1/sqrt(512)

    // 1) QKV projections: [8192,512] @ [512,512]
    {
        dim3 grid(DIM / BN, ROWS / BM, 1);
        sgemm_kernel<false, false><<<grid, 256>>>(x, Wq, Q, ROWS, DIM, DIM, 1.f, 0, 0, 0, nullptr, 0);
        sgemm_kernel<false, false><<<grid, 256>>>(x, Wk, K, ROWS, DIM, DIM, 1.f, 0, 0, 0, nullptr, 0);
        sgemm_kernel<false, false><<<grid, 256>>>(x, Wv, V, ROWS, DIM, DIM, 1.f, 0, 0, 0, nullptr, 0);
    }

    // 2) scores = (Q @ K^T) / sqrt(d) : per batch [4096,512] x [4096,512]^T
    {
        dim3 grid(SEQ / BN, SEQ / BM, BATCH);
        sgemm_kernel<true, false><<<grid, 256>>>(
            Q, K, P, SEQ, SEQ, DIM, inv_sqrt_d,
            (size_t)SEQ * DIM, (size_t)SEQ * DIM, (size_t)SEQ * SEQ, nullptr, 0);
    }

    // 3) softmax (exp + rowsum; normalization deferred)
    softmax_exp_kernel<<<ROWS, 256>>>(P, inv, SEQ);

    // 4) context = diag(1/rowsum) * (P @ V) : per batch [4096,4096] x [4096,512]
    {
        dim3 grid(DIM / BN, SEQ / BM, BATCH);
        sgemm_kernel<false, true><<<grid, 256>>>(
            P, V, out, SEQ, DIM, SEQ, 1.f,
            (size_t)SEQ * SEQ, (size_t)SEQ * DIM, (size_t)SEQ * DIM, inv, SEQ);
    }
}

// round 4
// speedup vs baseline: 2.5376x; 2.5376x over previous
#include <cuda_runtime.h>
#include <cuda_bf16.h>
#include <math.h>
#include <stdint.h>

// Problem constants
#define BATCH 2
#define SEQ   4096
#define DIM   512
#define ROWS  (BATCH * SEQ)          // 8192

typedef __nv_bfloat16 bf16;

// ---------------------------------------------------------------------------
// Device scratch (static globals — no allocations)
// ---------------------------------------------------------------------------
__device__ bf16  g_xh[ROWS * DIM],  g_xl[ROWS * DIM];
__device__ bf16  g_wth[3 * DIM * DIM], g_wtl[3 * DIM * DIM];   // W^T hi/lo
__device__ bf16  g_Qh[ROWS * DIM],  g_Ql[ROWS * DIM];
__device__ bf16  g_Kh[ROWS * DIM],  g_Kl[ROWS * DIM];
__device__ bf16  g_Vth[(size_t)BATCH * DIM * SEQ], g_Vtl[(size_t)BATCH * DIM * SEQ]; // V^T [b][512][4096]
__device__ float g_S[(size_t)BATCH * SEQ * SEQ];               // scores fp32
__device__ bf16  g_Ph[(size_t)BATCH * SEQ * SEQ], g_Pl[(size_t)BATCH * SEQ * SEQ];
__device__ float g_inv[ROWS];

// ---------------------------------------------------------------------------
// helpers (baseline sm_80+ PTX only — NO tcgen05 / 'a'-gated features)
// ---------------------------------------------------------------------------
__device__ __forceinline__ uint32_t smem_u32(const void* p) {
    uint32_t a;
    asm("{ .reg .u64 t; cvta.to.shared.u64 t, %1; cvt.u32.u64 %0, t; }" : "=r"(a) : "l"(p));
    return a;
}
#define CP16(dst, src) \
    asm volatile("cp.async.cg.shared.global [%0], [%1], 16;" :: "r"(dst), "l"(src))
#define CP_COMMIT() asm volatile("cp.async.commit_group;" ::: "memory")
#define CP_WAIT1()  asm volatile("cp.async.wait_group 1;" ::: "memory")
#define CP_WAIT0()  asm volatile("cp.async.wait_group 0;" ::: "memory")

__device__ __forceinline__ void ldm_x4(uint32_t* r, uint32_t addr) {
    asm volatile("ldmatrix.sync.aligned.m8n8.x4.shared.b16 {%0,%1,%2,%3}, [%4];"
        : "=r"(r[0]), "=r"(r[1]), "=r"(r[2]), "=r"(r[3]) : "r"(addr));
}
__device__ __forceinline__ void mma_bf16(float* c, const uint32_t* a, const uint32_t* b) {
    asm volatile(
        "mma.sync.aligned.m16n8k16.row.col.f32.bf16.bf16.f32 "
        "{%0,%1,%2,%3}, {%4,%5,%6,%7}, {%8,%9}, {%0,%1,%2,%3};"
        : "+f"(c[0]), "+f"(c[1]), "+f"(c[2]), "+f"(c[3])
        : "r"(a[0]), "r"(a[1]), "r"(a[2]), "r"(a[3]), "r"(b[0]), "r"(b[1]));
}
__device__ __forceinline__ void store_split2(bf16* h, bf16* l, float a, float b) {
    bf16 h0 = __float2bfloat16(a), h1 = __float2bfloat16(b);
    __nv_bfloat162 hp, lp;
    hp.x = h0; hp.y = h1;
    lp.x = __float2bfloat16(a - __bfloat162float(h0));
    lp.y = __float2bfloat16(b - __bfloat162float(h1));
    *(__nv_bfloat162*)h = hp;
    *(__nv_bfloat162*)l = lp;
}

// smem layout: per stage 4 arrays (Ah, Al, Bh, Bl), each 128 rows x 80 bytes
#define ARR    10240
#define STAGE  40960
#define SMEM_DYN (2 * STAGE)   // 81920 bytes

// ---------------------------------------------------------------------------
// NT GEMM via mma.sync: C[128x128] = sum_k A[m,k]*B[n,k], bf16 split 3-term.
// MODE 0: outF = val*alpha            (scores)
// MODE 1: outF = val*rowscale         (context)
// MODE 2: outH/L = bf16 split [m,n]   (Q/K projection)
// MODE 3: outH/L = bf16 split, n->(b,s): out[b][m][s]  (V^T projection)
// ---------------------------------------------------------------------------
template <int MODE>
__global__ __launch_bounds__(256, 2)
void mma_gemm(const bf16* __restrict__ Ah, const bf16* __restrict__ Al,
              const bf16* __restrict__ Bh, const bf16* __restrict__ Bl,
              int K, size_t strideA, size_t strideB,
              float alpha, const float* __restrict__ rowscale,
              float* __restrict__ outF, size_t strideOut, int ldOut,
              bf16* __restrict__ outH, bf16* __restrict__ outL)
{
    extern __shared__ char smem[];
    const uint32_t sb = smem_u32(smem);
    const int tid  = threadIdx.x;
    const int lane = tid & 31;
    const int wid  = tid >> 5;
    const int wm   = wid & 1;         // 2 warps along M
    const int wn   = wid >> 1;        // 4 warps along N
    const int m0 = blockIdx.y * 128;
    const int n0 = blockIdx.x * 128;
    const int z  = blockIdx.z;

    const bf16* aH = Ah + z * strideA + (size_t)m0 * K;
    const bf16* aL = Al + z * strideA + (size_t)m0 * K;
    const bf16* bH = Bh + z * strideB + (size_t)n0 * K;
    const bf16* bL = Bl + z * strideB + (size_t)n0 * K;

    float acc[4][4][4];
#pragma unroll
    for (int i = 0; i < 4; i++)
#pragma unroll
        for (int j = 0; j < 4; j++)
#pragma unroll
            for (int q = 0; q < 4; q++) acc[i][j][q] = 0.f;

    const int nc = K >> 5;   // 32-wide k chunks

    // ---- stage loader: 8 x 16B cp.async per thread ----
    auto load_stage = [&](int s, int k0) {
        const uint32_t base = sb + s * STAGE;
#pragma unroll
        for (int i = 0; i < 2; i++) {
            const int c   = tid + i * 256;
            const int row = c >> 2, kc = c & 3;
            const uint32_t doff = (uint32_t)(row * 80 + kc * 16);
            const size_t   soff = (size_t)row * K + k0 + kc * 8;
            CP16(base + 0 * ARR + doff, (const void*)(aH + soff));
            CP16(base + 1 * ARR + doff, (const void*)(aL + soff));
            CP16(base + 2 * ARR + doff, (const void*)(bH + soff));
            CP16(base + 3 * ARR + doff, (const void*)(bL + soff));
        }
    };

    load_stage(0, 0);
    CP_COMMIT();

    for (int c = 0; c < nc; c++) {
        if (c + 1 < nc) {
            load_stage((c + 1) & 1, (c + 1) << 5);
            CP_COMMIT();
            CP_WAIT1();
        } else {
            CP_WAIT0();
        }
        __syncthreads();

        const uint32_t s0 = sb + (c & 1) * STAGE;
#pragma unroll
        for (int ks = 0; ks < 2; ks++) {
            uint32_t ah[4][4], al[4][4];
#pragma unroll
            for (int mi = 0; mi < 4; mi++) {
                const uint32_t ad = s0 +
                    (uint32_t)((wm * 64 + mi * 16 + (lane & 15)) * 80 + ks * 32 + (lane >> 4) * 16);
                ldm_x4(ah[mi], ad);
                ldm_x4(al[mi], ad + ARR);
            }
#pragma unroll
            for (int bi = 0; bi < 2; bi++) {
                const uint32_t bd = s0 + 2 * ARR +
                    (uint32_t)((wn * 32 + bi * 16 + (lane & 15)) * 80 + ks * 32 + (lane >> 4) * 16);
                uint32_t bh[4], bl[4];
                ldm_x4(bh, bd);
                ldm_x4(bl, bd + ARR);
#pragma unroll
                for (int n2 = 0; n2 < 2; n2++) {
                    const int ni = bi * 2 + n2;
                    uint32_t bbh[2] = { bh[n2], bh[2 + n2] };
                    uint32_t bbl[2] = { bl[n2], bl[2 + n2] };
#pragma unroll
                    for (int mi = 0; mi < 4; mi++) mma_bf16(acc[mi][ni], ah[mi], bbh);  // hh
#pragma unroll
                    for (int mi = 0; mi < 4; mi++) mma_bf16(acc[mi][ni], al[mi], bbh);  // lh
#pragma unroll
                    for (int mi = 0; mi < 4; mi++) mma_bf16(acc[mi][ni], ah[mi], bbl);  // hl
                }
            }
        }
        __syncthreads();
    }

    // ---- epilogue ----
    const int r  = lane >> 2;
    const int cq = (lane & 3) * 2;
#pragma unroll
    for (int mi = 0; mi < 4; mi++) {
        const int row0 = m0 + wm * 64 + mi * 16 + r;   // second half row0+8
#pragma unroll
        for (int ni = 0; ni < 4; ni++) {
            const int col = n0 + wn * 32 + ni * 8 + cq;
            const float v00 = acc[mi][ni][0], v01 = acc[mi][ni][1];
            const float v10 = acc[mi][ni][2], v11 = acc[mi][ni][3];
            if (MODE == 0) {
                float* o0 = outF + z * strideOut + (size_t)row0 * ldOut + col;
                float* o1 = outF + z * strideOut + (size_t)(row0 + 8) * ldOut + col;
                *(float2*)o0 = make_float2(v00 * alpha, v01 * alpha);
                *(float2*)o1 = make_float2(v10 * alpha, v11 * alpha);
            } else if (MODE == 1) {
                const float s0 = rowscale[z * SEQ + row0];
                const float s1 = rowscale[z * SEQ + row0 + 8];
                float* o0 = outF + z * strideOut + (size_t)row0 * ldOut + col;
                float* o1 = outF + z * strideOut + (size_t)(row0 + 8) * ldOut + col;
                *(float2*)o0 = make_float2(v00 * s0, v01 * s0);
                *(float2*)o1 = make_float2(v10 * s1, v11 * s1);
            } else if (MODE == 2) {
                const size_t o0 = (size_t)row0 * ldOut + col;
                const size_t o1 = (size_t)(row0 + 8) * ldOut + col;
                store_split2(outH + o0, outL + o0, v00, v01);
                store_split2(outH + o1, outL + o1, v10, v11);
            } else {  // MODE 3: columns are x-rows (batch, seq); rows are d
                const int b = col >> 12, s = col & 4095;
                const size_t o0 = (size_t)b * DIM * SEQ + (size_t)row0 * SEQ + s;
                const size_t o1 = o0 + (size_t)8 * SEQ;
                store_split2(outH + o0, outL + o0, v00, v01);
                store_split2(outH + o1, outL + o1, v10, v11);
            }
        }
    }
}

// ---------------------------------------------------------------------------
// prep kernels
// ---------------------------------------------------------------------------
__global__ void split_f32(const float* __restrict__ in, bf16* __restrict__ h,
                          bf16* __restrict__ l, int n4)
{
    int i = blockIdx.x * blockDim.x + threadIdx.x;
    if (i >= n4) return;
    float4 v = ((const float4*)in)[i];
    bf16 h0 = __float2bfloat16(v.x), h1 = __float2bfloat16(v.y);
    bf16 h2 = __float2bfloat16(v.z), h3 = __float2bfloat16(v.w);
    __nv_bfloat162 hp0, hp1, lp0, lp1;
    hp0.x = h0; hp0.y = h1; hp1.x = h2; hp1.y = h3;
    lp0.x = __float2bfloat16(v.x - __bfloat162float(h0));
    lp0.y = __float2bfloat16(v.y - __bfloat162float(h1));
    lp1.x = __float2bfloat16(v.z - __bfloat162float(h2));
    lp1.y = __float2bfloat16(v.w - __bfloat162float(h3));
    ((__nv_bfloat162*)h)[i * 2 + 0] = hp0;
    ((__nv_bfloat162*)h)[i * 2 + 1] = hp1;
    ((__nv_bfloat162*)l)[i * 2 + 0] = lp0;
    ((__nv_bfloat162*)l)[i * 2 + 1] = lp1;
}

__global__ void transpose_split_w(const float* __restrict__ W,
                                  bf16* __restrict__ th, bf16* __restrict__ tl)
{
    int id = blockIdx.x * blockDim.x + threadIdx.x;   // 512*512
    if (id >= DIM * DIM) return;
    int k = id >> 9, n = id & 511;
    float v = W[id];
    bf16 h = __float2bfloat16(v);
    bf16 l = __float2bfloat16(v - __bfloat162float(h));
    th[n * DIM + k] = h;
    tl[n * DIM + k] = l;
}

// row softmax: fp32 scores -> bf16 hi/lo exp-weights + 1/rowsum
__global__ void softmax_split(const float* __restrict__ S, bf16* __restrict__ Ph,
                              bf16* __restrict__ Pl, float* __restrict__ inv, int n)
{
    __shared__ float red[256];
    const size_t row = blockIdx.x;
    const float* p = S + row * (size_t)n;
    const int tid = threadIdx.x;

    float m = -3.0e38f;
    for (int c = tid * 4; c < n; c += 1024) {
        float4 v = *(const float4*)&p[c];
        m = fmaxf(m, fmaxf(fmaxf(v.x, v.y), fmaxf(v.z, v.w)));
    }
    red[tid] = m; __syncthreads();
    for (int s = 128; s > 0; s >>= 1) {
        if (tid < s) red[tid] = fmaxf(red[tid], red[tid + s]);
        __syncthreads();
    }
    m = red[0]; __syncthreads();

    float sum = 0.f;
    bf16* oh = Ph + row * (size_t)n;
    bf16* ol = Pl + row * (size_t)n;
    for (int c = tid * 4; c < n; c += 1024) {
        float4 v = *(const float4*)&p[c];
        float e0 = __expf(v.x - m), e1 = __expf(v.y - m);
        float e2 = __expf(v.z - m), e3 = __expf(v.w - m);
        sum += e0 + e1 + e2 + e3;
        bf16 h0 = __float2bfloat16(e0), h1 = __float2bfloat16(e1);
        bf16 h2 = __float2bfloat16(e2), h3 = __float2bfloat16(e3);
        __nv_bfloat162 hp0, hp1, lp0, lp1;
        hp0.x = h0; hp0.y = h1; hp1.x = h2; hp1.y = h3;
        lp0.x = __float2bfloat16(e0 - __bfloat162float(h0));
        lp0.y = __float2bfloat16(e1 - __bfloat162float(h1));
        lp1.x = __float2bfloat16(e2 - __bfloat162float(h2));
        lp1.y = __float2bfloat16(e3 - __bfloat162float(h3));
        ((__nv_bfloat162*)oh)[c / 2 + 0] = hp0;
        ((__nv_bfloat162*)oh)[c / 2 + 1] = hp1;
        ((__nv_bfloat162*)ol)[c / 2 + 0] = lp0;
        ((__nv_bfloat162*)ol)[c / 2 + 1] = lp1;
    }
    red[tid] = sum; __syncthreads();
    for (int s = 128; s > 0; s >>= 1) {
        if (tid < s) red[tid] += red[tid + s];
        __syncthreads();
    }
    if (tid == 0) inv[row] = 1.0f / red[0];
}

// ---------------------------------------------------------------------------
extern "C" void kernel_launch(void* const* d_in, const int* in_sizes, int n_in,
                              void* d_out, int out_size)
{
    const float* x  = (const float*)d_in[0];
    const float* Wq = (const float*)d_in[1];
    const float* Wk = (const float*)d_in[2];
    const float* Wv = (const float*)d_in[3];
    float* out = (float*)d_out;

    bf16 *xh, *xl, *wth, *wtl, *Qh, *Ql, *Kh, *Kl, *Vth, *Vtl, *Ph, *Pl;
    float *S, *inv;
    cudaGetSymbolAddress((void**)&xh,  g_xh);  cudaGetSymbolAddress((void**)&xl,  g_xl);
    cudaGetSymbolAddress((void**)&wth, g_wth); cudaGetSymbolAddress((void**)&wtl, g_wtl);
    cudaGetSymbolAddress((void**)&Qh,  g_Qh);  cudaGetSymbolAddress((void**)&Ql,  g_Ql);
    cudaGetSymbolAddress((void**)&Kh,  g_Kh);  cudaGetSymbolAddress((void**)&Kl,  g_Kl);
    cudaGetSymbolAddress((void**)&Vth, g_Vth); cudaGetSymbolAddress((void**)&Vtl, g_Vtl);
    cudaGetSymbolAddress((void**)&S,   g_S);
    cudaGetSymbolAddress((void**)&Ph,  g_Ph);  cudaGetSymbolAddress((void**)&Pl,  g_Pl);
    cudaGetSymbolAddress((void**)&inv, g_inv);

    cudaFuncSetAttribute(mma_gemm<0>, cudaFuncAttributeMaxDynamicSharedMemorySize, SMEM_DYN);
    cudaFuncSetAttribute(mma_gemm<1>, cudaFuncAttributeMaxDynamicSharedMemorySize, SMEM_DYN);
    cudaFuncSetAttribute(mma_gemm<2>, cudaFuncAttributeMaxDynamicSharedMemorySize, SMEM_DYN);
    cudaFuncSetAttribute(mma_gemm<3>, cudaFuncAttributeMaxDynamicSharedMemorySize, SMEM_DYN);

    const float inv_sqrt_d = 0.04419417382415922f;  // 1/sqrt(512)

    // 0) split inputs to bf16 hi/lo
    split_f32<<<(ROWS * DIM / 4 + 255) / 256, 256>>>(x, xh, xl, ROWS * DIM / 4);
    transpose_split_w<<<(DIM * DIM + 255) / 256, 256>>>(Wq, wth + 0 * DIM * DIM, wtl + 0 * DIM * DIM);
    transpose_split_w<<<(DIM * DIM + 255) / 256, 256>>>(Wk, wth + 1 * DIM * DIM, wtl + 1 * DIM * DIM);
    transpose_split_w<<<(DIM * DIM + 255) / 256, 256>>>(Wv, wth + 2 * DIM * DIM, wtl + 2 * DIM * DIM);

    // 1) projections (NT). Q, K: [8192,512] x Wt. V: Wt x x^T -> V^T directly.
    {
        dim3 gq(DIM / 128, ROWS / 128, 1);
        mma_gemm<2><<<gq, 256, SMEM_DYN>>>(xh, xl, wth + 0 * DIM * DIM, wtl + 0 * DIM * DIM,
            DIM, 0, 0, 1.f, nullptr, nullptr, 0, DIM, Qh, Ql);
        mma_gemm<2><<<gq, 256, SMEM_DYN>>>(xh, xl, wth + 1 * DIM * DIM, wtl + 1 * DIM * DIM,
            DIM, 0, 0, 1.f, nullptr, nullptr, 0, DIM, Kh, Kl);
        dim3 gv(ROWS / 128, DIM / 128, 1);
        mma_gemm<3><<<gv, 256, SMEM_DYN>>>(wth + 2 * DIM * DIM, wtl + 2 * DIM * DIM, xh, xl,
            DIM, 0, 0, 1.f, nullptr, nullptr, 0, 0, Vth, Vtl);
    }

    // 2) scores = (Q @ K^T)/sqrt(d)
    {
        dim3 g(SEQ / 128, SEQ / 128, BATCH);
        mma_gemm<0><<<g, 256, SMEM_DYN>>>(Qh, Ql, Kh, Kl,
            DIM, (size_t)SEQ * DIM, (size_t)SEQ * DIM,
            inv_sqrt_d, nullptr, S, (size_t)SEQ * SEQ, SEQ, nullptr, nullptr);
    }

    // 3) softmax -> bf16 split weights + 1/rowsum
    softmax_split<<<ROWS, 256>>>(S, Ph, Pl, inv, SEQ);

    // 4) context = diag(1/rowsum) * (P @ V), B = V^T (K-major)
    {
        dim3 g(DIM / 128, SEQ / 128, BATCH);
        mma_gemm<1><<<g, 256, SMEM_DYN>>>(Ph, Pl, Vth, Vtl,
            SEQ, (size_t)SEQ * SEQ, (size_t)DIM * SEQ,
            1.f, inv, out, (size_t)SEQ * DIM, DIM, nullptr, nullptr);
    }
}